// round 1
// baseline (speedup 1.0000x reference)
#include <cuda_runtime.h>
#include <cuda_bf16.h>

// Problem constants
#define BB 2
#define NN 16384
#define CIN 64
#define SS 4096
#define NSAMP 32

// Output layout (floats): new_xyz | new_features | scores
#define OUT_XYZ_OFF   0
#define OUT_FEAT_OFF  (BB * SS * 3)                       // 24576
#define OUT_SCORE_OFF (OUT_FEAT_OFF + BB * 128 * SS)      // 1073152

// ---------------- scratch (no allocations allowed) ----------------
__device__ float g_featsT[BB * NN * CIN];    // (B,N,C) transposed features, 8 MB
__device__ int   g_ballIdx[BB * SS * NSAMP]; // neighbor indices
__device__ int   g_ballCnt[BB * SS];         // in-ball counts (0 => empty)

// =================================================================
// Kernel 1: farthest point sampling (one block per batch)
//  - xy coords in shared (float2), z + running min-dist in registers
//  - bit-exact distance: ((dx*dx + dy*dy) + dz*dz), no FMA contraction
//  - argmax with first-index tie-breaking (matches jnp.argmax)
// =================================================================
#define FPS_T 1024
#define FPS_P 16  // points per thread

__global__ __launch_bounds__(FPS_T) void fps_kernel(
    const float* __restrict__ xyz, float* __restrict__ out_newxyz)
{
    extern __shared__ float fsm[];
    float2* sxy = (float2*)fsm;           // 16384 float2 (128 KB)
    __shared__ float s_val[32];
    __shared__ int   s_idx[32];
    __shared__ int   s_far;

    const int b   = blockIdx.x;
    const int tid = threadIdx.x;
    const int lane = tid & 31, wid = tid >> 5;

    const float* xb = xyz + (size_t)b * NN * 3;

    float zreg[FPS_P];
    float dist[FPS_P];

    // load coords: xy -> smem, z -> registers (point i = k*1024 + tid)
    for (int i = tid; i < NN; i += FPS_T) {
        float x = xb[3 * i + 0];
        float y = xb[3 * i + 1];
        sxy[i] = make_float2(x, y);
    }
#pragma unroll
    for (int k = 0; k < FPS_P; k++) {
        int i = k * FPS_T + tid;
        zreg[k] = xb[3 * i + 2];
        dist[k] = 1e10f;
    }
    if (tid == 0) s_far = 0;
    __syncthreads();

    float* outx = out_newxyz + (size_t)b * SS * 3;

    for (int j = 0; j < SS; j++) {
        const int far = s_far;
        const float2 cxy = sxy[far];
        // centroid z: owner thread has it in a register; cheaper to reload from global? No:
        // read z from global once per iter by thread 0 would add latency. Keep a shared copy:
        // we reconstruct z via the owning thread writing it last iteration is complex; instead
        // read z from global with __ldg (L1-resident after first pass, broadcast).
        const float cz = __ldg(&xb[3 * far + 2]);

        if (tid == 0) {
            outx[3 * j + 0] = cxy.x;
            outx[3 * j + 1] = cxy.y;
            outx[3 * j + 2] = cz;
        }

        float best = -1.0f;
        int besti = 0;
#pragma unroll
        for (int k = 0; k < FPS_P; k++) {
            const int i = k * FPS_T + tid;
            const float2 p = sxy[i];
            const float dx = p.x - cxy.x;
            const float dy = p.y - cxy.y;
            const float dz = zreg[k] - cz;
            // exact: ((dx^2 + dy^2) + dz^2), round-to-nearest, no contraction
            const float d = __fadd_rn(__fadd_rn(__fmul_rn(dx, dx), __fmul_rn(dy, dy)),
                                      __fmul_rn(dz, dz));
            const float dm = fminf(dist[k], d);
            dist[k] = dm;
            if (dm > best) { best = dm; besti = i; }  // strict > keeps smallest index
        }

        // warp argmax reduce with first-index ties
#pragma unroll
        for (int off = 16; off; off >>= 1) {
            const float ov = __shfl_down_sync(0xffffffffu, best, off);
            const int   oi = __shfl_down_sync(0xffffffffu, besti, off);
            if (ov > best || (ov == best && oi < besti)) { best = ov; besti = oi; }
        }
        if (lane == 0) { s_val[wid] = best; s_idx[wid] = besti; }
        __syncthreads();
        if (wid == 0) {
            best  = s_val[lane];
            besti = s_idx[lane];
#pragma unroll
            for (int off = 16; off; off >>= 1) {
                const float ov = __shfl_down_sync(0xffffffffu, best, off);
                const int   oi = __shfl_down_sync(0xffffffffu, besti, off);
                if (ov > best || (ov == best && oi < besti)) { best = ov; besti = oi; }
            }
            if (lane == 0) s_far = besti;
        }
        __syncthreads();
    }
}

// =================================================================
// Kernel 2: transpose features (B,C,N) -> (B,N,C)
// =================================================================
__global__ void transpose_kernel(const float* __restrict__ f)
{
    __shared__ float tile[32][33];
    const int b  = blockIdx.z;
    const int n0 = blockIdx.x * 32;
    const int c0 = blockIdx.y * 32;
    const int tx = threadIdx.x, ty = threadIdx.y;
    tile[ty][tx] = f[((size_t)b * CIN + (c0 + ty)) * NN + n0 + tx];
    __syncthreads();
    g_featsT[((size_t)b * NN + (n0 + ty)) * CIN + c0 + tx] = tile[tx][ty];
}

// =================================================================
// Kernel 3: ball query (one warp per group), first-32-ascending
// =================================================================
__global__ void ballq_kernel(const float* __restrict__ xyz,
                             const float* __restrict__ newxyz)
{
    const int g    = blockIdx.x * 8 + (threadIdx.x >> 5);
    const int lane = threadIdx.x & 31;
    const int b    = g >> 12;
    const float* xb = xyz + (size_t)b * NN * 3;

    const float cx = newxyz[g * 3 + 0];
    const float cy = newxyz[g * 3 + 1];
    const float cz = newxyz[g * 3 + 2];

    int* out = g_ballIdx + g * NSAMP;
    int cnt = 0;

    for (int base = 0; base < NN && cnt < NSAMP; base += 32) {
        const int i = base + lane;
        const float dx = xb[3 * i + 0] - cx;
        const float dy = xb[3 * i + 1] - cy;
        const float dz = xb[3 * i + 2] - cz;
        const float d2 = __fadd_rn(__fadd_rn(__fmul_rn(dx, dx), __fmul_rn(dy, dy)),
                                   __fmul_rn(dz, dz));
        const bool inb = d2 < 0.25f;  // radius^2 = 0.25 exactly
        const unsigned m = __ballot_sync(0xffffffffu, inb);
        const int pos = cnt + __popc(m & ((1u << lane) - 1u));
        if (inb && pos < NSAMP) out[pos] = i;
        cnt += __popc(m);
    }
    __syncwarp();
    if (cnt == 0) {
        out[lane] = 0;
    } else if (cnt < NSAMP) {
        const int first = out[0];
        if (lane >= cnt) out[lane] = first;
    }
    if (lane == 0) g_ballCnt[g] = cnt;
}

// =================================================================
// Kernel 4: fused gather + 3-layer MLP + maxpool + agg + score
// One block (256 threads) per group.
// =================================================================
#define SM_INT_F   (67 * 36)
#define SM_W1_F    (67 * 64)
#define SM_W2_F    (64 * 64)
#define SM_W3_F    (64 * 128)
#define SM_H_F     (64 * 36)
#define MLP_SMEM_FLOATS (SM_INT_F + SM_W1_F + SM_W2_F + SM_W3_F + 2 * SM_H_F + 256 + 256 + 128 + 128 + 32)

__global__ __launch_bounds__(256, 2) void group_mlp_kernel(
    const float* __restrict__ xyz,
    const float* __restrict__ newxyz,
    const float* __restrict__ w1, const float* __restrict__ b1,
    const float* __restrict__ w2, const float* __restrict__ b2,
    const float* __restrict__ w3, const float* __restrict__ b3,
    const float* __restrict__ wa, const float* __restrict__ ba,
    const float* __restrict__ wc, const float* __restrict__ bc,
    float* __restrict__ d_out)
{
    extern __shared__ float sm[];
    float* inT     = sm;                    // [67][36]  input  (i-major, nb fast)
    float* w1s     = inT + SM_INT_F;        // [67][64]  (i-major, oc fast)
    float* w2s     = w1s + SM_W1_F;         // [64][64]
    float* w3s     = w2s + SM_W2_F;         // [64][128]
    float* h1T     = w3s + SM_W3_F;         // [64][36]
    float* h2T     = h1T + SM_H_F;          // [64][36]
    float* bss     = h2T + SM_H_F;          // b1[64] b2[64] b3[128]
    float* poolbuf = bss + 256;             // [128][2]
    float* pooled  = poolbuf + 256;         // [128]
    float* aggv    = pooled + 128;          // [128]
    int*   idxs    = (int*)(aggv + 128);    // [32]

    const int g = blockIdx.x;
    const int b = g >> 12;
    const int s = g & 4095;
    const int tid = threadIdx.x;

    // ---- stage indices, biases, weights (transposed) ----
    if (tid < 32)  idxs[tid] = g_ballIdx[g * NSAMP + tid];
    if (tid < 64)       bss[tid] = b1[tid];
    else if (tid < 128) bss[tid] = b2[tid - 64];
    if (tid < 128) bss[128 + tid] = b3[tid];

    for (int e = tid; e < 64 * 67; e += 256) {
        const int oc = e / 67, i = e % 67;
        w1s[i * 64 + oc] = w1[e];
    }
    for (int e = tid; e < 64 * 64; e += 256) {
        const int oc = e >> 6, i = e & 63;
        w2s[i * 64 + oc] = w2[e];
    }
    for (int e = tid; e < 128 * 64; e += 256) {
        const int oc = e >> 6, i = e & 63;
        w3s[i * 128 + oc] = w3[e];
    }
    __syncthreads();

    // ---- gather: inT[i][nb] = (i<3) ? xyz[idx]-center : featsT[idx][i-3] ----
    const float* xb = xyz + (size_t)b * NN * 3;
    const float cx = newxyz[g * 3 + 0];
    const float cy = newxyz[g * 3 + 1];
    const float cz = newxyz[g * 3 + 2];
    for (int e = tid; e < 32 * 67; e += 256) {
        const int nb = e & 31;
        const int i  = e >> 5;
        const int pi = idxs[nb];
        float v;
        if (i == 0)      v = xb[pi * 3 + 0] - cx;
        else if (i == 1) v = xb[pi * 3 + 1] - cy;
        else if (i == 2) v = xb[pi * 3 + 2] - cz;
        else             v = g_featsT[((size_t)b * NN + pi) * CIN + (i - 3)];
        inT[i * 36 + nb] = v;
    }
    __syncthreads();

    // ---- layer 1: 67 -> 64, ReLU ----
    {
        const int oc = tid & 63, ng = tid >> 6;  // 4 groups of 8 neighbors
        float acc[8];
        const float bv = bss[oc];
#pragma unroll
        for (int n = 0; n < 8; n++) acc[n] = bv;
        for (int i = 0; i < 67; i++) {
            const float w = w1s[i * 64 + oc];
            const float4* xp = (const float4*)(inT + i * 36 + ng * 8);
            const float4 x0 = xp[0], x1 = xp[1];
            acc[0] += w * x0.x; acc[1] += w * x0.y; acc[2] += w * x0.z; acc[3] += w * x0.w;
            acc[4] += w * x1.x; acc[5] += w * x1.y; acc[6] += w * x1.z; acc[7] += w * x1.w;
        }
        float* hp = h1T + oc * 36 + ng * 8;
#pragma unroll
        for (int n = 0; n < 8; n++) hp[n] = fmaxf(acc[n], 0.f);
    }
    __syncthreads();

    // ---- layer 2: 64 -> 64, ReLU ----
    {
        const int oc = tid & 63, ng = tid >> 6;
        float acc[8];
        const float bv = bss[64 + oc];
#pragma unroll
        for (int n = 0; n < 8; n++) acc[n] = bv;
        for (int i = 0; i < 64; i++) {
            const float w = w2s[i * 64 + oc];
            const float4* xp = (const float4*)(h1T + i * 36 + ng * 8);
            const float4 x0 = xp[0], x1 = xp[1];
            acc[0] += w * x0.x; acc[1] += w * x0.y; acc[2] += w * x0.z; acc[3] += w * x0.w;
            acc[4] += w * x1.x; acc[5] += w * x1.y; acc[6] += w * x1.z; acc[7] += w * x1.w;
        }
        float* hp = h2T + oc * 36 + ng * 8;
#pragma unroll
        for (int n = 0; n < 8; n++) hp[n] = fmaxf(acc[n], 0.f);
    }
    __syncthreads();

    // ---- layer 3: 64 -> 128, ReLU fused with local max over neighbors ----
    {
        const int oc = tid & 127, ng = tid >> 7;  // 2 groups of 16 neighbors
        float acc[16];
        const float bv = bss[128 + oc];
#pragma unroll
        for (int n = 0; n < 16; n++) acc[n] = bv;
        for (int i = 0; i < 64; i++) {
            const float w = w3s[i * 128 + oc];
            const float4* xp = (const float4*)(h2T + i * 36 + ng * 16);
            const float4 x0 = xp[0], x1 = xp[1], x2 = xp[2], x3 = xp[3];
            acc[0]  += w * x0.x; acc[1]  += w * x0.y; acc[2]  += w * x0.z; acc[3]  += w * x0.w;
            acc[4]  += w * x1.x; acc[5]  += w * x1.y; acc[6]  += w * x1.z; acc[7]  += w * x1.w;
            acc[8]  += w * x2.x; acc[9]  += w * x2.y; acc[10] += w * x2.z; acc[11] += w * x2.w;
            acc[12] += w * x3.x; acc[13] += w * x3.y; acc[14] += w * x3.z; acc[15] += w * x3.w;
        }
        float m = acc[0];
#pragma unroll
        for (int n = 1; n < 16; n++) m = fmaxf(m, acc[n]);
        m = fmaxf(m, 0.f);  // max(relu(x)) == relu(max(x))
        poolbuf[oc * 2 + ng] = m;
    }
    __syncthreads();

    const int cnt = g_ballCnt[g];
    if (tid < 128) {
        const float m = fmaxf(poolbuf[tid * 2], poolbuf[tid * 2 + 1]);
        pooled[tid] = (cnt > 0) ? m : 0.f;
    }
    __syncthreads();

    // ---- aggregation MLP: 128 -> 128, ReLU; write new_features ----
    if (tid < 128) {
        const int o = tid;
        float acc = ba[o];
        const float4* w4 = (const float4*)(wa + o * 128);
#pragma unroll 8
        for (int i = 0; i < 32; i++) {
            const float4 wv = __ldg(w4 + i);
            acc += pooled[4 * i + 0] * wv.x;
            acc += pooled[4 * i + 1] * wv.y;
            acc += pooled[4 * i + 2] * wv.z;
            acc += pooled[4 * i + 3] * wv.w;
        }
        const float a = fmaxf(acc, 0.f);
        aggv[o] = a;
        d_out[OUT_FEAT_OFF + ((size_t)(b * 128 + o)) * SS + s] = a;
    }
    __syncthreads();

    // ---- confidence score: wc . agg + bc ----
    if (tid < 32) {
        float p = 0.f;
#pragma unroll
        for (int k = 0; k < 4; k++) {
            const int i = k * 32 + tid;
            p += aggv[i] * wc[i];
        }
#pragma unroll
        for (int off = 16; off; off >>= 1)
            p += __shfl_down_sync(0xffffffffu, p, off);
        if (tid == 0)
            d_out[OUT_SCORE_OFF + b * SS + s] = p + bc[0];
    }
}

// =================================================================
// launch
// =================================================================
extern "C" void kernel_launch(void* const* d_in, const int* in_sizes, int n_in,
                              void* d_out, int out_size)
{
    const float* xyz      = (const float*)d_in[0];
    const float* features = (const float*)d_in[1];
    const float* w1 = (const float*)d_in[2];
    const float* b1 = (const float*)d_in[3];
    const float* w2 = (const float*)d_in[4];
    const float* b2 = (const float*)d_in[5];
    const float* w3 = (const float*)d_in[6];
    const float* b3 = (const float*)d_in[7];
    const float* wa = (const float*)d_in[8];
    const float* ba = (const float*)d_in[9];
    const float* wc = (const float*)d_in[10];
    const float* bc = (const float*)d_in[11];
    float* out = (float*)d_out;

    static bool attr_set = false;
    if (!attr_set) {
        cudaFuncSetAttribute(fps_kernel, cudaFuncAttributeMaxDynamicSharedMemorySize,
                             NN * (int)sizeof(float2));
        cudaFuncSetAttribute(group_mlp_kernel, cudaFuncAttributeMaxDynamicSharedMemorySize,
                             MLP_SMEM_FLOATS * (int)sizeof(float));
        attr_set = true;
    }

    // 1) FPS -> writes new_xyz into d_out[0:24576)
    fps_kernel<<<BB, FPS_T, NN * sizeof(float2)>>>(xyz, out + OUT_XYZ_OFF);

    // 2) transpose features to (B,N,C)
    transpose_kernel<<<dim3(NN / 32, CIN / 32, BB), dim3(32, 32)>>>(features);

    // 3) ball query
    ballq_kernel<<<(BB * SS) / 8, 256>>>(xyz, out + OUT_XYZ_OFF);

    // 4) fused gather + MLP + pool + agg + score
    group_mlp_kernel<<<BB * SS, 256, MLP_SMEM_FLOATS * sizeof(float)>>>(
        xyz, out + OUT_XYZ_OFF,
        w1, b1, w2, b2, w3, b3, wa, ba, wc, bc, out);
}